// round 12
// baseline (speedup 1.0000x reference)
#include <cuda_runtime.h>
#include <cuda_fp16.h>
#include <stdint.h>
#include <math.h>

#define B_DIM 256
#define K_DIM 4096

#define BM 256              // full batch per CTA
#define BN 128
#define BK 64               // K elements per stage
#define PHW 36              // A row pitch in words (64 halves + pad) — conflict-free
#define PBF 72              // B row pitch in floats (64 floats + pad) — conflict-free
#define A_STAGE_WORDS (BM * PHW)                      // 9216 w (36864 B)
#define B_STAGE_WORDS (BN * PBF)                      // 9216 w (36864 B)
#define STAGE_WORDS (A_STAGE_WORDS + B_STAGE_WORDS)   // 18432 w (73728 B)
#define NST 3
#define NTHREADS 256
#define SPLITK1 4
#define SPLITK2 4

// scratch (allocation-free rule)
__device__ float  g_part[4 * B_DIM * K_DIM];   // split-K partials (16 MB)
__device__ __half g_xh_h[2 * B_DIM * K_DIM];   // fp16 [x ; h0]
__device__ __half g_hn_h[B_DIM * K_DIM];       // fp16 hidden state

// ---------------- helpers ----------------

__device__ __forceinline__ uint32_t pack_f16x2(float lo, float hi) {
    uint32_t d;
    asm("cvt.rn.f16x2.f32 %0, %1, %2;" : "=r"(d) : "f"(hi), "f"(lo));
    return d;
}

__device__ __forceinline__ void mma16(float c[4], const uint32_t a[4], const uint32_t b[2]) {
    asm volatile(
        "mma.sync.aligned.m16n8k16.row.col.f32.f16.f16.f32 "
        "{%0,%1,%2,%3}, {%4,%5,%6,%7}, {%8,%9}, {%0,%1,%2,%3};\n"
        : "+f"(c[0]), "+f"(c[1]), "+f"(c[2]), "+f"(c[3])
        : "r"(a[0]), "r"(a[1]), "r"(a[2]), "r"(a[3]),
          "r"(b[0]), "r"(b[1]));
}

__device__ __forceinline__ void cp_async16(void* smem_dst, const void* gsrc) {
    unsigned s = (unsigned)__cvta_generic_to_shared(smem_dst);
    asm volatile("cp.async.cg.shared.global [%0], [%1], 16;\n" :: "r"(s), "l"(gsrc));
}
__device__ __forceinline__ void cp_commit() {
    asm volatile("cp.async.commit_group;\n");
}
template <int N>
__device__ __forceinline__ void cp_wait() {
    asm volatile("cp.async.wait_group %0;\n" :: "n"(N));
}

// ---------------- prep: convert x,h0 to fp16 once ----------------

__global__ void __launch_bounds__(256)
prep_kernel(const float* __restrict__ x, const float* __restrict__ h0) {
    size_t e = ((size_t)blockIdx.x * 256 + threadIdx.x) * 4;
    const size_t half_n = (size_t)B_DIM * K_DIM;
    const float* src = (e < half_n) ? (x + e) : (h0 + (e - half_n));
    float4 p = *(const float4*)src;
    uint2 o;
    o.x = pack_f16x2(p.x, p.y);
    o.y = pack_f16x2(p.z, p.w);
    *(uint2*)(g_xh_h + e) = o;
}

// ---------------- GEMM (split-K partial, fp16 HMMA, warp 64x64, NST=3 single-barrier) ----------------

template <int GEMM>
__global__ void __launch_bounds__(NTHREADS, 1)
gemm_splitk_kernel(const float* __restrict__ w0, const float* __restrict__ w1,
                   int KT) {
    extern __shared__ uint32_t smw[];   // 3 stages: [A 9216 w][B 9216 w]

    const int t = threadIdx.x;
    const int z = blockIdx.z;
    const int bx = blockIdx.x;

    // resolve split-K sources
    const __half* Ah;
    const float* Bw;
    size_t koff;
    if (GEMM == 1) {
        Ah = g_xh_h + (z >= 2 ? (size_t)B_DIM * K_DIM : 0);
        Bw = (z < 2) ? w0 : w1;
        koff = (size_t)(z & 1) * (K_DIM / 2);            // 2048
    } else {
        Ah = g_hn_h; Bw = w0;
        koff = (size_t)z * (K_DIM / SPLITK2);            // 1024
    }

    // load geometry
    // A: 2048 vec16/stage (256 rows x 8), 8 per thread; rows step +32
    const int arow = t >> 3, avc = t & 7;
    const __half* srcA = Ah + (size_t)arow * K_DIM + koff + avc * 8;
    uint32_t* dstA = smw + arow * PHW + avc * 4;
    // B: 2048 vec16/stage (128 rows x 16), 8 per thread; rows step +16
    const int brow = t >> 4, bvc = t & 15;
    const float* srcB = Bw + ((size_t)(bx * BN + brow)) * K_DIM + koff + bvc * 4;
    uint32_t* dstB = smw + A_STAGE_WORDS + brow * PBF + bvc * 4;

    float acc[4][8][4];
#pragma unroll
    for (int i = 0; i < 4; i++)
#pragma unroll
        for (int j = 0; j < 8; j++)
#pragma unroll
            for (int k = 0; k < 4; k++) acc[i][j][k] = 0.0f;

    const int lane = t & 31, warp = t >> 5;
    const int wm = (warp >> 1) * 64;    // 4 warps along M
    const int wn = (warp & 1) * 64;     // 2 warps along N (64 cols each)
    const int g = lane >> 2, tc = lane & 3;

    // prologue: stages 0,1
#pragma unroll
    for (int s = 0; s < 2; s++) {
        uint32_t* da = dstA + s * STAGE_WORDS;
        uint32_t* db = dstB + s * STAGE_WORDS;
        size_t ko = (size_t)s * BK;
#pragma unroll
        for (int i = 0; i < 8; i++) cp_async16(da + i * 32 * PHW, srcA + ko + (size_t)i * 32 * K_DIM);
#pragma unroll
        for (int i = 0; i < 8; i++) cp_async16(db + i * 16 * PBF, srcB + ko + (size_t)i * 16 * K_DIM);
        cp_commit();
    }

#pragma unroll 1
    for (int kt = 0; kt < KT; kt++) {
        // stage kt ready (leave kt+1 in flight when it exists)
        if (kt + 1 < KT) cp_wait<1>(); else cp_wait<0>();
        __syncthreads();   // deposits visible; all warps done with compute kt-1
                           // -> buffer (kt+2)%3 (consumed at kt-1) is free

        if (kt + 2 < KT) {
            const int sl = (kt + 2) % NST;
            uint32_t* da = dstA + sl * STAGE_WORDS;
            uint32_t* db = dstB + sl * STAGE_WORDS;
            size_t ko = (size_t)(kt + 2) * BK;
#pragma unroll
            for (int i = 0; i < 8; i++) cp_async16(da + i * 32 * PHW, srcA + ko + (size_t)i * 32 * K_DIM);
#pragma unroll
            for (int i = 0; i < 8; i++) cp_async16(db + i * 16 * PBF, srcB + ko + (size_t)i * 16 * K_DIM);
            cp_commit();
        }

        const uint32_t* Aw = smw + (kt % NST) * STAGE_WORDS;
        const float*    Bf = (const float*)(Aw + A_STAGE_WORDS);
#pragma unroll
        for (int ks2 = 0; ks2 < 4; ks2++) {    // four k16 steps per BK=64
            uint32_t a[4][4];
#pragma unroll
            for (int mi = 0; mi < 4; mi++) {
                int r = wm + mi * 16 + g;
                int base = ks2 * 8 + tc;
                a[mi][0] = Aw[r * PHW + base];
                a[mi][1] = Aw[(r + 8) * PHW + base];
                a[mi][2] = Aw[r * PHW + base + 4];
                a[mi][3] = Aw[(r + 8) * PHW + base + 4];
            }
            uint32_t b[8][2];
#pragma unroll
            for (int ni = 0; ni < 8; ni++) {
                int r = wn + ni * 8 + g;
                const float* bp = Bf + r * PBF + ks2 * 16 + 2 * tc;
                float2 p0 = *(const float2*)bp;
                float2 p1 = *(const float2*)(bp + 8);
                b[ni][0] = pack_f16x2(p0.x, p0.y);
                b[ni][1] = pack_f16x2(p1.x, p1.y);
            }
#pragma unroll
            for (int mi = 0; mi < 4; mi++)
#pragma unroll
                for (int ni = 0; ni < 8; ni++)
                    mma16(acc[mi][ni], a[mi], b[ni]);
        }
        // no bottom barrier: next iteration's top barrier orders buffer reuse
    }

    // write partial tile
    float* part = g_part + (size_t)z * (B_DIM * K_DIM);
#pragma unroll
    for (int mi = 0; mi < 4; mi++) {
#pragma unroll
        for (int ni = 0; ni < 8; ni++) {
            int gr = wm + mi * 16 + g;
            int gc = bx * BN + wn + ni * 8 + tc * 2;
            size_t o0 = (size_t)gr * K_DIM + gc;
            size_t o2 = (size_t)(gr + 8) * K_DIM + gc;
            *(float2*)(part + o0) = make_float2(acc[mi][ni][0], acc[mi][ni][1]);
            *(float2*)(part + o2) = make_float2(acc[mi][ni][2], acc[mi][ni][3]);
        }
    }
}

// ---------------- reduce1: hn = tanh(sum partials + bih + bhh) ----------------

__global__ void __launch_bounds__(256)
reduce1_kernel(const float* __restrict__ bih, const float* __restrict__ bhh,
               float* __restrict__ hn_out) {
    size_t e = ((size_t)blockIdx.x * 256 + threadIdx.x) * 4;
    int col = (int)(e & (K_DIM - 1));
    float4 p0 = *(const float4*)(g_part + e);
    float4 p1 = *(const float4*)(g_part + (size_t)1 * B_DIM * K_DIM + e);
    float4 p2 = *(const float4*)(g_part + (size_t)2 * B_DIM * K_DIM + e);
    float4 p3 = *(const float4*)(g_part + (size_t)3 * B_DIM * K_DIM + e);
    float4 ba = *(const float4*)(bih + col);
    float4 bb = *(const float4*)(bhh + col);
    float t0 = tanhf(p0.x + p1.x + p2.x + p3.x + ba.x + bb.x);
    float t1 = tanhf(p0.y + p1.y + p2.y + p3.y + ba.y + bb.y);
    float t2 = tanhf(p0.z + p1.z + p2.z + p3.z + ba.z + bb.z);
    float t3 = tanhf(p0.w + p1.w + p2.w + p3.w + ba.w + bb.w);
    *(float4*)(hn_out + e) = make_float4(t0, t1, t2, t3);
    uint2 o;
    o.x = pack_f16x2(t0, t1);
    o.y = pack_f16x2(t2, t3);
    *(uint2*)(g_hn_h + e) = o;
}

// ---------------- softmax (fuses GEMM2 split-K reduce + bias) ----------------

#define SMT 512

__global__ void __launch_bounds__(SMT)
softmax_kernel(const float* __restrict__ blin, float* __restrict__ probs) {
    __shared__ float sl[K_DIM];
    __shared__ float red[SMT];
    const int row = blockIdx.x, tid = threadIdx.x;
    const size_t rb = (size_t)row * K_DIM;

    float m = -1e30f;
    for (int i = tid * 4; i < K_DIM; i += SMT * 4) {
        float4 p0 = *(const float4*)(g_part + rb + i);
        float4 p1 = *(const float4*)(g_part + (size_t)1 * B_DIM * K_DIM + rb + i);
        float4 p2 = *(const float4*)(g_part + (size_t)2 * B_DIM * K_DIM + rb + i);
        float4 p3 = *(const float4*)(g_part + (size_t)3 * B_DIM * K_DIM + rb + i);
        float4 b  = *(const float4*)(blin + i);
        float v0 = p0.x + p1.x + p2.x + p3.x + b.x;
        float v1 = p0.y + p1.y + p2.y + p3.y + b.y;
        float v2 = p0.z + p1.z + p2.z + p3.z + b.z;
        float v3 = p0.w + p1.w + p2.w + p3.w + b.w;
        *(float4*)(sl + i) = make_float4(v0, v1, v2, v3);
        m = fmaxf(m, fmaxf(fmaxf(v0, v1), fmaxf(v2, v3)));
    }
    red[tid] = m;
    __syncthreads();
    for (int s = SMT / 2; s > 0; s >>= 1) {
        if (tid < s) red[tid] = fmaxf(red[tid], red[tid + s]);
        __syncthreads();
    }
    m = red[0];
    __syncthreads();

    float sum = 0.0f;
    for (int i = tid; i < K_DIM; i += SMT) sum += expf(sl[i] - m);
    red[tid] = sum;
    __syncthreads();
    for (int s = SMT / 2; s > 0; s >>= 1) {
        if (tid < s) red[tid] += red[tid + s];
        __syncthreads();
    }
    float inv = 1.0f / red[0];

    for (int i = tid; i < K_DIM; i += SMT)
        probs[rb + i] = expf(sl[i] - m) * inv;
}

// ---------------- launch ----------------

extern "C" void kernel_launch(void* const* d_in, const int* in_sizes, int n_in,
                              void* d_out, int out_size) {
    const float* x    = (const float*)d_in[0];
    const float* h0   = (const float*)d_in[1];
    const float* wih  = (const float*)d_in[2];
    const float* bih  = (const float*)d_in[3];
    const float* whh  = (const float*)d_in[4];
    const float* bhh  = (const float*)d_in[5];
    const float* wlin = (const float*)d_in[6];
    const float* blin = (const float*)d_in[7];

    float* out = (float*)d_out;
    float* probs_out = out;
    float* hn_out    = out + (size_t)B_DIM * K_DIM;

    const int dyn = NST * STAGE_WORDS * sizeof(uint32_t);   // 221184 B
    cudaFuncSetAttribute(gemm_splitk_kernel<1>, cudaFuncAttributeMaxDynamicSharedMemorySize, dyn);
    cudaFuncSetAttribute(gemm_splitk_kernel<2>, cudaFuncAttributeMaxDynamicSharedMemorySize, dyn);

    // convert x,h0 to fp16 once
    prep_kernel<<<(2 * B_DIM * K_DIM) / (256 * 4), 256>>>(x, h0);

    // GEMM1: partials of x@wih^T + h0@whh^T (fused K=8192, split 4)
    dim3 grid1(K_DIM / BN, 1, SPLITK1);    // (32,1,4) = 128 CTAs
    gemm_splitk_kernel<1><<<grid1, NTHREADS, dyn>>>(wih, whh, (K_DIM / 2) / BK);  // KT=32

    reduce1_kernel<<<(B_DIM * K_DIM) / (256 * 4), 256>>>(bih, bhh, hn_out);

    // GEMM2: partials of hn@wlin^T (K=4096, split 4)
    dim3 grid2(K_DIM / BN, 1, SPLITK2);
    gemm_splitk_kernel<2><<<grid2, NTHREADS, dyn>>>(wlin, nullptr, (K_DIM / SPLITK2) / BK);  // KT=16

    softmax_kernel<<<B_DIM, SMT>>>(blin, probs_out);
}